// round 4
// baseline (speedup 1.0000x reference)
#include <cuda_runtime.h>

// ESH sampler: B rows, D=64, n_steps of 2 half-steps each.
// Layout: 16 lanes per row (group), 2 rows per warp, 4 elems (1 float4) per lane.
// Lane-in-group p owns float4 chunk p -> each warp store instruction covers
// 2 adjacent rows * 256B = 512B contiguous, fully coalesced.
//
// Algebra: u_new = Bc*u + ((Bc*ude - A)/||g||)*g, cond=false branch folded via
// Bs=0, Cc=1/||g||. u carried unnormalized with scalar scale `us`; materialized
// only at store time. x stores issued right after the drift update (x is final
// there) to spread DRAM traffic across the second half_step's compute.

__device__ __forceinline__ float grp_sum16(float v) {
    v += __shfl_xor_sync(0xffffffffu, v, 1);
    v += __shfl_xor_sync(0xffffffffu, v, 2);
    v += __shfl_xor_sync(0xffffffffu, v, 4);
    v += __shfl_xor_sync(0xffffffffu, v, 8);
    return v;
}

__device__ __forceinline__ void half_step(
    const float4& xv, float4& uv, const float4& pv,
    float& us, float& r, float ed)
{
    // grad = prec * x ; partial sums of ||g||^2 and u_raw . g
    float4 g;
    float gsq = 0.0f, ugr = 0.0f;
    g.x = pv.x * xv.x; gsq = fmaf(g.x, g.x, gsq); ugr = fmaf(uv.x, g.x, ugr);
    g.y = pv.y * xv.y; gsq = fmaf(g.y, g.y, gsq); ugr = fmaf(uv.y, g.y, ugr);
    g.z = pv.z * xv.z; gsq = fmaf(g.z, g.z, gsq); ugr = fmaf(uv.z, g.z, ugr);
    g.w = pv.w * xv.w; gsq = fmaf(g.w, g.w, gsq); ugr = fmaf(uv.w, g.w, ugr);
    gsq = grp_sum16(gsq);
    ugr = grp_sum16(ugr);

    float rs     = rsqrtf(fmaxf(gsq, 1e-20f));   // == 1/gn0
    float g_norm = fminf(gsq * rs, 10.0f);
    float ude    = -(us * ugr) * rs;             // u_true . grad_e
    float t      = __expf(-ed * g_norm);         // exp(-e*g/d)
    float A2     = (ude - 1.0f) * (t * t);
    float opu    = 1.0f + ude;
    float A      = opu + A2;
    bool  cond   = ude > -0.999f;
    float Bc     = 2.0f * t;
    float Bs     = cond ? Bc * us : 0.0f;                  // coeff on u_raw
    float Cc     = cond ? fmaf(Bc, ude, -A) * rs : rs;     // coeff on g

    float nsq = 0.0f;
    float un;
    un = fmaf(Cc, g.x, Bs * uv.x); uv.x = un; nsq = fmaf(un, un, nsq);
    un = fmaf(Cc, g.y, Bs * uv.y); uv.y = un; nsq = fmaf(un, un, nsq);
    un = fmaf(Cc, g.z, Bs * uv.z); uv.z = un; nsq = fmaf(un, un, nsq);
    un = fmaf(Cc, g.w, Bs * uv.w); uv.w = un; nsq = fmaf(un, un, nsq);
    nsq = grp_sum16(nsq);
    us  = rsqrtf(fmaxf(nsq, 1e-20f));            // new scale: u_true = us * u_raw

    float Z  = opu - A2;
    float dr = cond ? fmaf(ed, g_norm, __logf(0.5f * fmaxf(Z, 1e-10f)))
                    : -ed * g_norm;
    r += dr;
}

__global__ __launch_bounds__(256, 6)
void esh_kernel(const float* __restrict__ x0,
                const float* __restrict__ u0,
                const float* __restrict__ prec,
                const float* __restrict__ eps_p,
                const int* __restrict__ nsteps_p,
                float* __restrict__ out,
                int B)
{
    const int tid  = threadIdx.x;
    const int lane = tid & 31;
    const int p    = lane & 15;      // lane within group (16 per row)
    const int grp  = lane >> 4;      // 0..1 : row within warp
    const int warp = tid >> 5;       // 0..7
    const int row  = blockIdx.x * 16 + warp * 2 + grp;
    if (row >= B) return;

    const float eps = *eps_p;
    const int n_steps = *nsteps_p;
    const float ed = (0.5f * eps) * (1.0f / 64.0f);  // e/d, e = eps/2

    float4 xv, uv, pv;
    {
        const float4* xp = reinterpret_cast<const float4*>(x0 + (size_t)row * 64);
        const float4* up = reinterpret_cast<const float4*>(u0 + (size_t)row * 64);
        const float4* pp = reinterpret_cast<const float4*>(prec);
        xv = xp[p];
        uv = up[p];
        pv = pp[p];
    }
    float r = 0.0f;
    float us = 1.0f;   // u_true = us * uv

    const size_t rowstride = (size_t)B * 64;
    const size_t XN = (size_t)(n_steps + 1) * rowstride;
    float* outr = out + 2 * XN + row;

    // step 0: x0, u0, r0=0
    float4* ox = reinterpret_cast<float4*>(out + (size_t)row * 64);
    float4* ou = reinterpret_cast<float4*>(out + XN + (size_t)row * 64);
    __stcs(&ox[p], xv);
    __stcs(&ou[p], uv);
    if (p == 0) __stcs(outr, 0.0f);

    const size_t f4stride = rowstride / 4;  // float4 elements per step

    for (int s = 1; s <= n_steps; s++) {
        half_step(xv, uv, pv, us, r, ed);
        // x += eps * u_true  (fold us into the coefficient); x is final for
        // this step -> store it now, overlapping with the second half_step.
        {
            const float c = eps * us;
            xv.x = fmaf(c, uv.x, xv.x);
            xv.y = fmaf(c, uv.y, xv.y);
            xv.z = fmaf(c, uv.z, xv.z);
            xv.w = fmaf(c, uv.w, xv.w);
        }
        ox += f4stride;
        __stcs(&ox[p], xv);

        half_step(xv, uv, pv, us, r, ed);

        ou += f4stride;
        outr += B;
        // materialize normalized u and store
        {
            float4 w;
            w.x = us * uv.x; w.y = us * uv.y;
            w.z = us * uv.z; w.w = us * uv.w;
            uv = w;
            __stcs(&ou[p], w);
        }
        us = 1.0f;
        if (p == 0) __stcs(outr, r);
    }
}

extern "C" void kernel_launch(void* const* d_in, const int* in_sizes, int n_in,
                              void* d_out, int out_size)
{
    const float* x0     = (const float*)d_in[0];
    const float* u0     = (const float*)d_in[1];
    const float* prec   = (const float*)d_in[2];
    const float* eps_p  = (const float*)d_in[3];
    const int*   nsteps = (const int*)d_in[4];
    float* out = (float*)d_out;

    int B = in_sizes[0] / 64;
    int rows_per_block = 16;  // 256 threads, 8 warps, 2 rows/warp
    int grid = (B + rows_per_block - 1) / rows_per_block;
    esh_kernel<<<grid, 256>>>(x0, u0, prec, eps_p, nsteps, out, B);
}

// round 5
// speedup vs baseline: 1.2341x; 1.2341x over previous
#include <cuda_runtime.h>

// ESH sampler: B rows, D=64, n_steps of 2 half-steps each.
// Layout: 8 lanes per row (group), 4 rows per warp, 8 elems (2 float4) per lane.
// Lane-in-group p owns float4 chunks {p, p+8}.
//
// Key optimization: grad is evaluated at the SAME x in the 2nd half-step of
// step s and the 1st half-step of step s+1 (x only changes at the drift).
// So g, ||g||^2, rs=1/||g||, g_norm, t=exp(-e*g/d) are computed once per
// drift (compute_g) and reused across the step boundary — value-identical
// to the reference, ~18% fewer instructions.
//
// u carried unnormalized with scalar scale `us` (normalize folded into the
// scalar coefficients); materialized only at store time. x stored right
// after the drift to spread DRAM traffic.

__device__ __forceinline__ float grp_sum8(float v) {
    v += __shfl_xor_sync(0xffffffffu, v, 1);
    v += __shfl_xor_sync(0xffffffffu, v, 2);
    v += __shfl_xor_sync(0xffffffffu, v, 4);
    return v;
}

// g = prec*x and all scalars that depend only on g.
__device__ __forceinline__ void compute_g(
    const float4 (&xv)[2], const float4 (&pv)[2],
    float4 (&g)[2], float& rs, float& gn, float& t2, float& Bc, float ed)
{
    float gsq = 0.0f;
#pragma unroll
    for (int j = 0; j < 2; j++) {
        g[j].x = pv[j].x * xv[j].x; gsq = fmaf(g[j].x, g[j].x, gsq);
        g[j].y = pv[j].y * xv[j].y; gsq = fmaf(g[j].y, g[j].y, gsq);
        g[j].z = pv[j].z * xv[j].z; gsq = fmaf(g[j].z, g[j].z, gsq);
        g[j].w = pv[j].w * xv[j].w; gsq = fmaf(g[j].w, g[j].w, gsq);
    }
    gsq = grp_sum8(gsq);
    rs = rsqrtf(fmaxf(gsq, 1e-20f));     // == 1/||g||
    gn = fminf(gsq * rs, 10.0f);         // clamped norm
    float t = __expf(-ed * gn);          // exp(-e*g/d)
    t2 = t * t;
    Bc = 2.0f * t;
}

// Momentum/r update given precomputed g and scalars.
__device__ __forceinline__ void update_ur(
    const float4 (&g)[2], float4 (&uv)[2],
    float& us, float& r, float rs, float gn, float t2, float Bc, float ed)
{
    float ugr = 0.0f;
#pragma unroll
    for (int j = 0; j < 2; j++) {
        ugr = fmaf(uv[j].x, g[j].x, ugr);
        ugr = fmaf(uv[j].y, g[j].y, ugr);
        ugr = fmaf(uv[j].z, g[j].z, ugr);
        ugr = fmaf(uv[j].w, g[j].w, ugr);
    }
    ugr = grp_sum8(ugr);

    float ude  = -(us * ugr) * rs;            // u_true . grad_e
    float A2   = (ude - 1.0f) * t2;
    float opu  = 1.0f + ude;
    float A    = opu + A2;
    bool  cond = ude > -0.999f;
    float Bs   = cond ? Bc * us : 0.0f;                  // coeff on u_raw
    float Cc   = cond ? fmaf(Bc, ude, -A) * rs : rs;     // coeff on g

    float nsq = 0.0f;
#pragma unroll
    for (int j = 0; j < 2; j++) {
        float un;
        un = fmaf(Cc, g[j].x, Bs * uv[j].x); uv[j].x = un; nsq = fmaf(un, un, nsq);
        un = fmaf(Cc, g[j].y, Bs * uv[j].y); uv[j].y = un; nsq = fmaf(un, un, nsq);
        un = fmaf(Cc, g[j].z, Bs * uv[j].z); uv[j].z = un; nsq = fmaf(un, un, nsq);
        un = fmaf(Cc, g[j].w, Bs * uv[j].w); uv[j].w = un; nsq = fmaf(un, un, nsq);
    }
    nsq = grp_sum8(nsq);
    us  = rsqrtf(fmaxf(nsq, 1e-20f));         // u_true = us * u_raw

    float Z  = opu - A2;
    float dr = cond ? fmaf(ed, gn, __logf(0.5f * fmaxf(Z, 1e-10f)))
                    : -ed * gn;
    r += dr;
}

__global__ __launch_bounds__(256, 4)
void esh_kernel(const float* __restrict__ x0,
                const float* __restrict__ u0,
                const float* __restrict__ prec,
                const float* __restrict__ eps_p,
                const int* __restrict__ nsteps_p,
                float* __restrict__ out,
                int B)
{
    const int tid  = threadIdx.x;
    const int lane = tid & 31;
    const int p    = lane & 7;       // lane within group (8 per row)
    const int grp  = lane >> 3;      // 0..3 : row within warp
    const int warp = tid >> 5;       // 0..7
    const int row  = blockIdx.x * 32 + warp * 4 + grp;
    if (row >= B) return;

    const float eps = *eps_p;
    const int n_steps = *nsteps_p;
    const float ed = (0.5f * eps) * (1.0f / 64.0f);  // e/d, e = eps/2

    float4 xv[2], uv[2], pv[2];
    {
        const float4* xp = reinterpret_cast<const float4*>(x0 + (size_t)row * 64);
        const float4* up = reinterpret_cast<const float4*>(u0 + (size_t)row * 64);
        const float4* pp = reinterpret_cast<const float4*>(prec);
#pragma unroll
        for (int j = 0; j < 2; j++) {
            xv[j] = xp[p + 8 * j];
            uv[j] = up[p + 8 * j];
            pv[j] = pp[p + 8 * j];
        }
    }
    float r = 0.0f;
    float us = 1.0f;   // u_true = us * uv

    const size_t rowstride = (size_t)B * 64;
    const size_t XN = (size_t)(n_steps + 1) * rowstride;
    float* outr = out + 2 * XN + row;

    // step 0: x0, u0, r0=0
    float4* ox = reinterpret_cast<float4*>(out + (size_t)row * 64);
    float4* ou = reinterpret_cast<float4*>(out + XN + (size_t)row * 64);
#pragma unroll
    for (int j = 0; j < 2; j++) {
        __stcs(&ox[p + 8 * j], xv[j]);
        __stcs(&ou[p + 8 * j], uv[j]);
    }
    if (p == 0) __stcs(outr, 0.0f);

    const size_t f4stride = rowstride / 4;  // float4 elements per step

    // gradient state at current x (reused across step boundary)
    float4 g[2];
    float rs, gn, t2, Bc;
    compute_g(xv, pv, g, rs, gn, t2, Bc, ed);

    for (int s = 1; s <= n_steps; s++) {
        // first half-step: uses g at undrifted x (carried over)
        update_ur(g, uv, us, r, rs, gn, t2, Bc, ed);

        // drift: x += eps * u_true ; x is final for this step -> store now
        {
            const float c = eps * us;
#pragma unroll
            for (int j = 0; j < 2; j++) {
                xv[j].x = fmaf(c, uv[j].x, xv[j].x);
                xv[j].y = fmaf(c, uv[j].y, xv[j].y);
                xv[j].z = fmaf(c, uv[j].z, xv[j].z);
                xv[j].w = fmaf(c, uv[j].w, xv[j].w);
            }
        }
        ox += f4stride;
#pragma unroll
        for (int j = 0; j < 2; j++) __stcs(&ox[p + 8 * j], xv[j]);

        // gradient at drifted x (also serves next iteration's first half-step)
        compute_g(xv, pv, g, rs, gn, t2, Bc, ed);

        // second half-step
        update_ur(g, uv, us, r, rs, gn, t2, Bc, ed);

        ou += f4stride;
        outr += B;
        // materialize normalized u and store
#pragma unroll
        for (int j = 0; j < 2; j++) {
            float4 w;
            w.x = us * uv[j].x; w.y = us * uv[j].y;
            w.z = us * uv[j].z; w.w = us * uv[j].w;
            uv[j] = w;
            __stcs(&ou[p + 8 * j], w);
        }
        us = 1.0f;
        if (p == 0) __stcs(outr, r);
    }
}

extern "C" void kernel_launch(void* const* d_in, const int* in_sizes, int n_in,
                              void* d_out, int out_size)
{
    const float* x0     = (const float*)d_in[0];
    const float* u0     = (const float*)d_in[1];
    const float* prec   = (const float*)d_in[2];
    const float* eps_p  = (const float*)d_in[3];
    const int*   nsteps = (const int*)d_in[4];
    float* out = (float*)d_out;

    int B = in_sizes[0] / 64;
    int rows_per_block = 32;  // 256 threads, 8 warps, 4 rows/warp
    int grid = (B + rows_per_block - 1) / rows_per_block;
    esh_kernel<<<grid, 256>>>(x0, u0, prec, eps_p, nsteps, out, B);
}